// round 1
// baseline (speedup 1.0000x reference)
#include <cuda_runtime.h>

#define NF   40
#define DIM  64
#define AD   32
#define NP   780          // 40*39/2
#define XSTR 68           // padded row stride (floats) to avoid bank degeneracy
#define BLK  256

// Packed fp32x2 FMA / MUL (Blackwell sm_100+ only, PTX-only path)
__device__ __forceinline__ float2 ffma2(float2 a, float2 b, float2 c) {
    float2 d;
    asm("fma.rn.f32x2 %0, %1, %2, %3;"
        : "=l"(reinterpret_cast<unsigned long long&>(d))
        : "l"(reinterpret_cast<unsigned long long&>(a)),
          "l"(reinterpret_cast<unsigned long long&>(b)),
          "l"(reinterpret_cast<unsigned long long&>(c)));
    return d;
}
__device__ __forceinline__ float2 fmul2(float2 a, float2 b) {
    float2 d;
    asm("mul.rn.f32x2 %0, %1, %2;"
        : "=l"(reinterpret_cast<unsigned long long&>(d))
        : "l"(reinterpret_cast<unsigned long long&>(a)),
          "l"(reinterpret_cast<unsigned long long&>(b)));
    return d;
}

__global__ __launch_bounds__(BLK, 2)
void afm_kernel(const float* __restrict__ inputs,   // [B, 40, 64]
                const float* __restrict__ W1,       // [64, 32]
                const float* __restrict__ b1,       // [32]
                const float* __restrict__ w2,       // [32]
                const float* __restrict__ pvec,     // [64]
                float* __restrict__ out)            // [B]
{
    __shared__ __align__(16) float  xs[NF * XSTR];       // 10880 B
    __shared__ __align__(16) float2 w1p[(DIM / 2) * AD]; // 8192 B, [d2*32 + a]
    __shared__ __align__(16) float  ps[DIM];
    __shared__ float b1s[AD], w2s[AD];
    __shared__ unsigned short pridx[NP];                 // (i<<8)|j
    __shared__ float lsm[NP];                            // logits
    __shared__ float csm[NP];                            // c_p = prod_p . p
    __shared__ float red[32];
    __shared__ float bcast;

    const int b = blockIdx.x;
    const int t = threadIdx.x;

    // ---- cooperative loads ----
    const float* xin = inputs + (size_t)b * (NF * DIM);
    for (int idx = t; idx < NF * DIM; idx += BLK) {
        int r = idx >> 6, c = idx & 63;
        xs[r * XSTR + c] = xin[idx];
    }
    // repack W1 [64][32] -> float2 over adjacent d: w1p[d2*32+a] = (W1[2d2][a], W1[2d2+1][a])
    for (int idx = t; idx < (DIM / 2) * AD; idx += BLK) {
        int d2 = idx >> 5, a = idx & 31;
        w1p[idx] = make_float2(W1[(2 * d2) * AD + a], W1[(2 * d2 + 1) * AD + a]);
    }
    if (t < DIM) ps[t] = pvec[t];
    if (t < AD) { b1s[t] = b1[t]; w2s[t] = w2[t]; }
    // pair table: row i of the strict upper triangle
    if (t < NF - 1) {
        int i = t;
        int base = i * (2 * NF - 1 - i) / 2;   // = i*(79-i)/2
        for (int j = i + 1; j < NF; j++)
            pridx[base + (j - i - 1)] = (unsigned short)((i << 8) | j);
    }
    __syncthreads();

    // ---- per-pair compute: logit[p] and c[p] ----
    for (int p0 = t; p0 < NP; p0 += BLK) {
        unsigned pp = pridx[p0];
        const float* xi = xs + (pp >> 8) * XSTR;
        const float* xj = xs + (pp & 255) * XSTR;

        float2 prod[DIM / 2];
        float2 ca0 = make_float2(0.f, 0.f), ca1 = make_float2(0.f, 0.f);
        #pragma unroll
        for (int k = 0; k < 16; k++) {
            float4 a4 = *(const float4*)(xi + 4 * k);
            float4 b4 = *(const float4*)(xj + 4 * k);
            float4 p4 = *(const float4*)(ps + 4 * k);
            float2 lo = fmul2(make_float2(a4.x, a4.y), make_float2(b4.x, b4.y));
            float2 hi = fmul2(make_float2(a4.z, a4.w), make_float2(b4.z, b4.w));
            prod[2 * k]     = lo;
            prod[2 * k + 1] = hi;
            ca0 = ffma2(lo, make_float2(p4.x, p4.y), ca0);
            ca1 = ffma2(hi, make_float2(p4.z, p4.w), ca1);
        }
        float cval = (ca0.x + ca0.y) + (ca1.x + ca1.y);

        float logit = 0.f;
        #pragma unroll 1
        for (int a = 0; a < AD; a++) {
            // 4 independent FFMA2 chains over the 32 packed d-pairs
            float2 ac0 = make_float2(0.f, 0.f), ac1 = make_float2(0.f, 0.f);
            float2 ac2 = make_float2(0.f, 0.f), ac3 = make_float2(0.f, 0.f);
            #pragma unroll
            for (int d2 = 0; d2 < 8; d2++) {
                ac0 = ffma2(prod[d2],      w1p[(d2)      * AD + a], ac0);
                ac1 = ffma2(prod[d2 + 8],  w1p[(d2 + 8)  * AD + a], ac1);
                ac2 = ffma2(prod[d2 + 16], w1p[(d2 + 16) * AD + a], ac2);
                ac3 = ffma2(prod[d2 + 24], w1p[(d2 + 24) * AD + a], ac3);
            }
            float s = ((ac0.x + ac0.y) + (ac1.x + ac1.y))
                    + ((ac2.x + ac2.y) + (ac3.x + ac3.y)) + b1s[a];
            logit = fmaf(fmaxf(s, 0.f), w2s[a], logit);
        }
        lsm[p0] = logit;
        csm[p0] = cval;
    }
    __syncthreads();

    // ---- softmax max over 780 logits ----
    float m = -1e30f;
    for (int p0 = t; p0 < NP; p0 += BLK) m = fmaxf(m, lsm[p0]);
    #pragma unroll
    for (int o = 16; o; o >>= 1) m = fmaxf(m, __shfl_xor_sync(0xffffffffu, m, o));
    if ((t & 31) == 0) red[t >> 5] = m;
    __syncthreads();
    if (t < 32) {
        float v = (t < BLK / 32) ? red[t] : -1e30f;
        #pragma unroll
        for (int o = 4; o; o >>= 1) v = fmaxf(v, __shfl_xor_sync(0xffffffffu, v, o));
        if (t == 0) bcast = v;
    }
    __syncthreads();
    const float M = bcast;

    // ---- sum(exp) and weighted sum in one pass ----
    float s = 0.f, ws = 0.f;
    for (int p0 = t; p0 < NP; p0 += BLK) {
        float e = __expf(lsm[p0] - M);
        s += e;
        ws = fmaf(e, csm[p0], ws);
    }
    #pragma unroll
    for (int o = 16; o; o >>= 1) {
        s  += __shfl_xor_sync(0xffffffffu, s, o);
        ws += __shfl_xor_sync(0xffffffffu, ws, o);
    }
    if ((t & 31) == 0) { red[t >> 5] = s; red[16 + (t >> 5)] = ws; }
    __syncthreads();
    if (t == 0) {
        float S = 0.f, WS = 0.f;
        #pragma unroll
        for (int w = 0; w < BLK / 32; w++) { S += red[w]; WS += red[16 + w]; }
        out[b] = WS / S;
    }
}

extern "C" void kernel_launch(void* const* d_in, const int* in_sizes, int n_in,
                              void* d_out, int out_size)
{
    const float* inputs = (const float*)d_in[0];
    const float* W1     = (const float*)d_in[1];
    const float* b1     = (const float*)d_in[2];
    const float* w2     = (const float*)d_in[3];
    const float* pvec   = (const float*)d_in[4];
    float* out = (float*)d_out;

    int B = in_sizes[0] / (NF * DIM);   // 8192
    afm_kernel<<<B, BLK>>>(inputs, W1, b1, w2, pvec, out);
}

// round 2
// speedup vs baseline: 1.4275x; 1.4275x over previous
#include <cuda_runtime.h>

#define NF    40
#define DIM   64
#define AD    32
#define NP    780
#define XSTR  68          // xs row stride (floats)
#define W1STR 33          // w1s row stride (floats)
#define BLK   256
#define CH    128         // pairs per chunk
#define NCH   7           // 7*128 = 896 >= 780

// ---- helpers ----
__device__ __forceinline__ float tf32r(float x) {
    unsigned u;
    asm("cvt.rna.tf32.f32 %0, %1;" : "=r"(u) : "f"(x));
    return __uint_as_float(u);
}

__device__ __forceinline__ void mma_tf32(float& d0, float& d1, float& d2, float& d3,
                                         unsigned a0, unsigned a1, unsigned a2, unsigned a3,
                                         unsigned b0, unsigned b1) {
    asm("mma.sync.aligned.m16n8k8.row.col.f32.tf32.tf32.f32 "
        "{%0,%1,%2,%3}, {%4,%5,%6,%7}, {%8,%9}, {%0,%1,%2,%3};"
        : "+f"(d0), "+f"(d1), "+f"(d2), "+f"(d3)
        : "r"(a0), "r"(a1), "r"(a2), "r"(a3), "r"(b0), "r"(b1));
}

// swizzled float index of (row, col) in a [128 x 64] f32 tile, 8-float granules
__device__ __forceinline__ int swz(int row, int col) {
    return row * 64 + ((((col >> 3) ^ row) & 7) << 3) + (col & 7);
}

__global__ __launch_bounds__(BLK, 2)
void afm_kernel(const float* __restrict__ inputs,   // [B, 40, 64]
                const float* __restrict__ W1,       // [64, 32]
                const float* __restrict__ b1,       // [32]
                const float* __restrict__ w2,       // [32]
                const float* __restrict__ pvec,     // [64]
                float* __restrict__ out)            // [B]
{
    extern __shared__ __align__(16) unsigned char dsm[];
    float* xs     = (float*)dsm;                 // 40*68   = 2720
    float* prodHi = xs + NF * XSTR;              // 128*64  = 8192
    float* prodLo = prodHi + CH * DIM;           // 8192
    float* w1s    = prodLo + CH * DIM;           // 64*33   = 2112
    float* lsm    = w1s + DIM * W1STR;           // 896
    float* csm    = lsm + 896;                   // 896
    float* ps     = csm + 896;                   // 64
    float* b1s    = ps + DIM;                    // 32
    float* w2s    = b1s + AD;                    // 32
    float* red    = w2s + AD;                    // 64
    unsigned short* pridx = (unsigned short*)(red + 64);   // 780

    const int b = blockIdx.x;
    const int t = threadIdx.x;
    const int lane = t & 31;
    const int w = t >> 5;
    const int q = lane & 3;          // 0..3
    const int g = lane >> 2;         // 0..7

    // ---------------- init loads ----------------
    const float* xin = inputs + (size_t)b * (NF * DIM);
    for (int idx = t; idx < NF * DIM; idx += BLK) {
        int r = idx >> 6, c = idx & 63;
        xs[r * XSTR + c] = xin[idx];
    }
    for (int idx = t; idx < DIM * AD; idx += BLK) {
        int k = idx >> 5, n = idx & 31;
        w1s[k * W1STR + n] = tf32r(W1[idx]);   // pre-round W1 to tf32
    }
    if (t < DIM) ps[t] = pvec[t];
    if (t < AD) { b1s[t] = b1[t]; w2s[t] = w2[t]; }
    if (t < NF - 1) {
        int i = t;
        int base = i * (2 * NF - 1 - i) / 2;
        for (int j = i + 1; j < NF; j++)
            pridx[base + (j - i - 1)] = (unsigned short)((i << 8) | j);
    }
    __syncthreads();

    // ---------------- chunk loop: produce prod tile, MMA, logits ----------------
    for (int ch = 0; ch < NCH; ch++) {
        const int base = ch * CH;

        // ---- producer: 2 threads per pair, each does 32 cols ----
        {
            const int pl = t >> 1;            // local row 0..127
            const int hf = t & 1;             // half
            const int p  = base + pl;
            float cacc = 0.f;
            const bool real = (p < NP);
            if (real) {
                unsigned pp = pridx[p];
                const float* xi = xs + (pp >> 8) * XSTR + hf * 32;
                const float* xj = xs + (pp & 255) * XSTR + hf * 32;
                const float* pv = ps + hf * 32;
                #pragma unroll
                for (int kk = 0; kk < 8; kk++) {
                    float4 a4 = *(const float4*)(xi + 4 * kk);
                    float4 b4 = *(const float4*)(xj + 4 * kk);
                    float4 v4 = *(const float4*)(pv + 4 * kk);
                    float4 pr;
                    pr.x = a4.x * b4.x; pr.y = a4.y * b4.y;
                    pr.z = a4.z * b4.z; pr.w = a4.w * b4.w;
                    cacc = fmaf(pr.x, v4.x, cacc);
                    cacc = fmaf(pr.y, v4.y, cacc);
                    cacc = fmaf(pr.z, v4.z, cacc);
                    cacc = fmaf(pr.w, v4.w, cacc);
                    float4 hi, lo;
                    hi.x = tf32r(pr.x); hi.y = tf32r(pr.y);
                    hi.z = tf32r(pr.z); hi.w = tf32r(pr.w);
                    lo.x = tf32r(pr.x - hi.x); lo.y = tf32r(pr.y - hi.y);
                    lo.z = tf32r(pr.z - hi.z); lo.w = tf32r(pr.w - hi.w);
                    int idx = swz(pl, hf * 32 + 4 * kk);   // float4 stays in one granule
                    *(float4*)(prodHi + idx) = hi;
                    *(float4*)(prodLo + idx) = lo;
                }
            } else {
                float4 z = make_float4(0.f, 0.f, 0.f, 0.f);
                #pragma unroll
                for (int kk = 0; kk < 8; kk++) {
                    int idx = swz(pl, hf * 32 + 4 * kk);
                    *(float4*)(prodHi + idx) = z;
                    *(float4*)(prodLo + idx) = z;
                }
            }
            cacc += __shfl_xor_sync(0xffffffffu, cacc, 1);
            if (real && hf == 0) csm[p] = cacc;
        }
        __syncthreads();

        // ---- consumer: warp w owns local rows [w*16, w*16+16) ----
        {
            const int R = w * 16;
            float acc[4][4];
            #pragma unroll
            for (int nt = 0; nt < 4; nt++)
                #pragma unroll
                for (int r = 0; r < 4; r++) acc[nt][r] = 0.f;

            #pragma unroll
            for (int kt = 0; kt < 8; kt++) {
                const int c0 = kt * 8 + q, c1 = c0 + 4;
                unsigned ah0 = __float_as_uint(prodHi[swz(R + g,     c0)]);
                unsigned ah1 = __float_as_uint(prodHi[swz(R + g + 8, c0)]);
                unsigned ah2 = __float_as_uint(prodHi[swz(R + g,     c1)]);
                unsigned ah3 = __float_as_uint(prodHi[swz(R + g + 8, c1)]);
                unsigned al0 = __float_as_uint(prodLo[swz(R + g,     c0)]);
                unsigned al1 = __float_as_uint(prodLo[swz(R + g + 8, c0)]);
                unsigned al2 = __float_as_uint(prodLo[swz(R + g,     c1)]);
                unsigned al3 = __float_as_uint(prodLo[swz(R + g + 8, c1)]);
                #pragma unroll
                for (int nt = 0; nt < 4; nt++) {
                    unsigned bb0 = __float_as_uint(w1s[(kt * 8 + q)     * W1STR + nt * 8 + g]);
                    unsigned bb1 = __float_as_uint(w1s[(kt * 8 + q + 4) * W1STR + nt * 8 + g]);
                    mma_tf32(acc[nt][0], acc[nt][1], acc[nt][2], acc[nt][3],
                             ah0, ah1, ah2, ah3, bb0, bb1);
                    mma_tf32(acc[nt][0], acc[nt][1], acc[nt][2], acc[nt][3],
                             al0, al1, al2, al3, bb0, bb1);
                }
            }

            // epilogue: relu(h + b1) . w2 -> logits for rows R+g and R+g+8
            float s0 = 0.f, s1 = 0.f;
            #pragma unroll
            for (int nt = 0; nt < 4; nt++) {
                const int cc0 = nt * 8 + 2 * q, cc1 = cc0 + 1;
                float ba = b1s[cc0], bb = b1s[cc1];
                float wa = w2s[cc0], wb = w2s[cc1];
                s0 = fmaf(fmaxf(acc[nt][0] + ba, 0.f), wa, s0);
                s0 = fmaf(fmaxf(acc[nt][1] + bb, 0.f), wb, s0);
                s1 = fmaf(fmaxf(acc[nt][2] + ba, 0.f), wa, s1);
                s1 = fmaf(fmaxf(acc[nt][3] + bb, 0.f), wb, s1);
            }
            s0 += __shfl_xor_sync(0xffffffffu, s0, 1);
            s0 += __shfl_xor_sync(0xffffffffu, s0, 2);
            s1 += __shfl_xor_sync(0xffffffffu, s1, 1);
            s1 += __shfl_xor_sync(0xffffffffu, s1, 2);
            if (q == 0) {
                int p0 = base + R + g;
                if (p0 < NP) lsm[p0] = s0;
                int p1 = p0 + 8;
                if (p1 < NP) lsm[p1] = s1;
            }
        }
        __syncthreads();
    }

    // ---------------- softmax max ----------------
    float m = -1e30f;
    for (int p0 = t; p0 < NP; p0 += BLK) m = fmaxf(m, lsm[p0]);
    #pragma unroll
    for (int o = 16; o; o >>= 1) m = fmaxf(m, __shfl_xor_sync(0xffffffffu, m, o));
    if (lane == 0) red[w] = m;
    __syncthreads();
    if (t < 32) {
        float v = (t < BLK / 32) ? red[t] : -1e30f;
        #pragma unroll
        for (int o = 4; o; o >>= 1) v = fmaxf(v, __shfl_xor_sync(0xffffffffu, v, o));
        if (t == 0) red[48] = v;
    }
    __syncthreads();
    const float M = red[48];

    // ---------------- sum(exp) + weighted sum ----------------
    float s = 0.f, ws = 0.f;
    for (int p0 = t; p0 < NP; p0 += BLK) {
        float e = __expf(lsm[p0] - M);
        s += e;
        ws = fmaf(e, csm[p0], ws);
    }
    #pragma unroll
    for (int o = 16; o; o >>= 1) {
        s  += __shfl_xor_sync(0xffffffffu, s, o);
        ws += __shfl_xor_sync(0xffffffffu, ws, o);
    }
    if (lane == 0) { red[w] = s; red[16 + w] = ws; }
    __syncthreads();
    if (t == 0) {
        float S = 0.f, WS = 0.f;
        #pragma unroll
        for (int ww = 0; ww < BLK / 32; ww++) { S += red[ww]; WS += red[16 + ww]; }
        out[b] = WS / S;
    }
}

extern "C" void kernel_launch(void* const* d_in, const int* in_sizes, int n_in,
                              void* d_out, int out_size)
{
    const float* inputs = (const float*)d_in[0];
    const float* W1     = (const float*)d_in[1];
    const float* b1     = (const float*)d_in[2];
    const float* w2     = (const float*)d_in[3];
    const float* pvec   = (const float*)d_in[4];
    float* out = (float*)d_out;

    // dynamic smem size (floats): xs 2720 + hi 8192 + lo 8192 + w1s 2112
    //  + lsm 896 + csm 896 + ps 64 + b1 32 + w2 32 + red 64 = 23200 floats
    //  + pridx 780*2 bytes
    const int smem_bytes = 23200 * 4 + 780 * 2 + 64;
    cudaFuncSetAttribute(afm_kernel, cudaFuncAttributeMaxDynamicSharedMemorySize, smem_bytes);

    int B = in_sizes[0] / (NF * DIM);   // 8192
    afm_kernel<<<B, BLK, smem_bytes>>>(inputs, W1, b1, w2, pvec, out);
}

// round 3
// speedup vs baseline: 5.1935x; 3.6382x over previous
#include <cuda_runtime.h>
#include <cuda_fp16.h>

#define NF    40
#define DIM   64
#define AD    32
#define NP    780
#define XSTR  68
#define BLK   128
#define NWARP (BLK / 32)
#define NTILE 49          // ceil(780 / 16)

__device__ __forceinline__ unsigned h2u(__half2 h) {
    return *reinterpret_cast<unsigned*>(&h);
}

__device__ __forceinline__ void mma_f16(float* acc,
                                        unsigned a0, unsigned a1, unsigned a2, unsigned a3,
                                        unsigned b0, unsigned b1) {
    asm("mma.sync.aligned.m16n8k16.row.col.f32.f16.f16.f32 "
        "{%0,%1,%2,%3}, {%4,%5,%6,%7}, {%8,%9}, {%0,%1,%2,%3};"
        : "+f"(acc[0]), "+f"(acc[1]), "+f"(acc[2]), "+f"(acc[3])
        : "r"(a0), "r"(a1), "r"(a2), "r"(a3), "r"(b0), "r"(b1));
}

__global__ __launch_bounds__(BLK, 4)
void afm_kernel(const float* __restrict__ inputs,   // [B, 40, 64]
                const float* __restrict__ W1,       // [64, 32]
                const float* __restrict__ b1,       // [32]
                const float* __restrict__ w2,       // [32]
                const float* __restrict__ pvec,     // [64]
                float* __restrict__ out)            // [B]
{
    __shared__ __align__(16) float xs[NF * XSTR];
    __shared__ float lsm[NP];
    __shared__ float csm[NP];
    __shared__ float ps[DIM], b1s[AD], w2s[AD];
    __shared__ float red[2 * NWARP + 2];
    __shared__ unsigned short pridx[NP];

    const int b    = blockIdx.x;
    const int t    = threadIdx.x;
    const int lane = t & 31;
    const int w    = t >> 5;
    const int q    = lane & 3;     // 0..3
    const int g    = lane >> 2;    // 0..7

    // ---------------- init: xs, params, pair table ----------------
    const float4* xin4 = (const float4*)(inputs + (size_t)b * (NF * DIM));
    #pragma unroll
    for (int idx = t; idx < NF * DIM / 4; idx += BLK) {
        float4 v = xin4[idx];
        int r = idx >> 4, c = (idx & 15) << 2;
        *(float4*)(xs + r * XSTR + c) = v;
    }
    if (t < DIM) ps[t] = pvec[t];
    if (t < AD) { b1s[t] = b1[t]; w2s[t] = w2[t]; }
    if (t < NF - 1) {
        int i = t;
        int base = i * (2 * NF - 1 - i) / 2;
        for (int j = i + 1; j < NF; j++)
            pridx[base + (j - i - 1)] = (unsigned short)((i << 8) | j);
    }

    // ---------------- B (W1) fragments in registers, fp16 hi/lo ----------------
    unsigned bh[4][4][2], bl[4][4][2];
    #pragma unroll
    for (int kt = 0; kt < 4; kt++)
        #pragma unroll
        for (int r = 0; r < 2; r++) {
            const int k0 = kt * 16 + 2 * q + 8 * r;
            #pragma unroll
            for (int nt = 0; nt < 4; nt++) {
                const int n = nt * 8 + g;
                float w0 = W1[k0 * AD + n];
                float w1v = W1[(k0 + 1) * AD + n];
                __half2 h = __floats2half2_rn(w0, w1v);
                float2 hf = __half22float2(h);
                __half2 l = __floats2half2_rn(w0 - hf.x, w1v - hf.y);
                bh[kt][nt][r] = h2u(h);
                bl[kt][nt][r] = h2u(l);
            }
        }
    __syncthreads();

    // ---------------- mainloop: independent M-tiles per warp ----------------
    for (int tile = w; tile < NTILE; tile += NWARP) {
        const int pA = tile * 16 + g;       // row g of tile
        const int pB = pA + 8;              // row g+8
        const unsigned ppA = pridx[pA < NP ? pA : NP - 1];
        const unsigned ppB = pridx[pB < NP ? pB : NP - 1];
        const float* xiA = xs + (ppA >> 8) * XSTR;
        const float* xjA = xs + (ppA & 255) * XSTR;
        const float* xiB = xs + (ppB >> 8) * XSTR;
        const float* xjB = xs + (ppB & 255) * XSTR;

        float acc[4][4];
        #pragma unroll
        for (int nt = 0; nt < 4; nt++)
            #pragma unroll
            for (int r = 0; r < 4; r++) acc[nt][r] = 0.f;

        float cpA = 0.f, cpB = 0.f;

        #pragma unroll
        for (int kt = 0; kt < 4; kt++) {
            const int c0 = kt * 16 + 2 * q;
            const int c8 = c0 + 8;

            // fp32 products for this lane's fragment elements
            float2 xA0 = *(const float2*)(xiA + c0), yA0 = *(const float2*)(xjA + c0);
            float2 xA8 = *(const float2*)(xiA + c8), yA8 = *(const float2*)(xjA + c8);
            float2 xB0 = *(const float2*)(xiB + c0), yB0 = *(const float2*)(xjB + c0);
            float2 xB8 = *(const float2*)(xiB + c8), yB8 = *(const float2*)(xjB + c8);
            float prA0 = xA0.x * yA0.x, prA1 = xA0.y * yA0.y;
            float prA8 = xA8.x * yA8.x, prA9 = xA8.y * yA8.y;
            float prB0 = xB0.x * yB0.x, prB1 = xB0.y * yB0.y;
            float prB8 = xB8.x * yB8.x, prB9 = xB8.y * yB8.y;

            // fold pooling scalar c_p = prod . pvec
            float2 pv0 = *(const float2*)(ps + c0);
            float2 pv8 = *(const float2*)(ps + c8);
            cpA = fmaf(prA0, pv0.x, cpA); cpA = fmaf(prA1, pv0.y, cpA);
            cpA = fmaf(prA8, pv8.x, cpA); cpA = fmaf(prA9, pv8.y, cpA);
            cpB = fmaf(prB0, pv0.x, cpB); cpB = fmaf(prB1, pv0.y, cpB);
            cpB = fmaf(prB8, pv8.x, cpB); cpB = fmaf(prB9, pv8.y, cpB);

            // split to fp16 hi/lo
            __half2 hA0 = __floats2half2_rn(prA0, prA1);
            __half2 hA8 = __floats2half2_rn(prA8, prA9);
            __half2 hB0 = __floats2half2_rn(prB0, prB1);
            __half2 hB8 = __floats2half2_rn(prB8, prB9);
            float2 fA0 = __half22float2(hA0), fA8 = __half22float2(hA8);
            float2 fB0 = __half22float2(hB0), fB8 = __half22float2(hB8);
            __half2 lA0 = __floats2half2_rn(prA0 - fA0.x, prA1 - fA0.y);
            __half2 lA8 = __floats2half2_rn(prA8 - fA8.x, prA9 - fA8.y);
            __half2 lB0 = __floats2half2_rn(prB0 - fB0.x, prB1 - fB0.y);
            __half2 lB8 = __floats2half2_rn(prB8 - fB8.x, prB9 - fB8.y);

            // A fragment regs: a0=row g k0..1, a1=row g+8 k0..1, a2=row g k8..9, a3=row g+8 k8..9
            unsigned ah0 = h2u(hA0), ah1 = h2u(hB0), ah2 = h2u(hA8), ah3 = h2u(hB8);
            unsigned al0 = h2u(lA0), al1 = h2u(lB0), al2 = h2u(lA8), al3 = h2u(lB8);

            #pragma unroll
            for (int nt = 0; nt < 4; nt++) {
                mma_f16(acc[nt], ah0, ah1, ah2, ah3, bh[kt][nt][0], bh[kt][nt][1]);
                mma_f16(acc[nt], al0, al1, al2, al3, bh[kt][nt][0], bh[kt][nt][1]);
                mma_f16(acc[nt], ah0, ah1, ah2, ah3, bl[kt][nt][0], bl[kt][nt][1]);
            }
        }

        // epilogue: relu(h + b1) . w2
        float s0 = 0.f, s1 = 0.f;
        #pragma unroll
        for (int nt = 0; nt < 4; nt++) {
            const int cc0 = nt * 8 + 2 * q, cc1 = cc0 + 1;
            float ba = b1s[cc0], bb = b1s[cc1];
            float wa = w2s[cc0], wb = w2s[cc1];
            s0 = fmaf(fmaxf(acc[nt][0] + ba, 0.f), wa, s0);
            s0 = fmaf(fmaxf(acc[nt][1] + bb, 0.f), wb, s0);
            s1 = fmaf(fmaxf(acc[nt][2] + ba, 0.f), wa, s1);
            s1 = fmaf(fmaxf(acc[nt][3] + bb, 0.f), wb, s1);
        }
        // reduce across the 4 q-lanes of each row group
        s0  += __shfl_xor_sync(0xffffffffu, s0, 1);
        s0  += __shfl_xor_sync(0xffffffffu, s0, 2);
        s1  += __shfl_xor_sync(0xffffffffu, s1, 1);
        s1  += __shfl_xor_sync(0xffffffffu, s1, 2);
        cpA += __shfl_xor_sync(0xffffffffu, cpA, 1);
        cpA += __shfl_xor_sync(0xffffffffu, cpA, 2);
        cpB += __shfl_xor_sync(0xffffffffu, cpB, 1);
        cpB += __shfl_xor_sync(0xffffffffu, cpB, 2);
        if (q == 0) {
            if (pA < NP) { lsm[pA] = s0; csm[pA] = cpA; }
            if (pB < NP) { lsm[pB] = s1; csm[pB] = cpB; }
        }
    }
    __syncthreads();

    // ---------------- softmax max ----------------
    float m = -1e30f;
    for (int p0 = t; p0 < NP; p0 += BLK) m = fmaxf(m, lsm[p0]);
    #pragma unroll
    for (int o = 16; o; o >>= 1) m = fmaxf(m, __shfl_xor_sync(0xffffffffu, m, o));
    if (lane == 0) red[w] = m;
    __syncthreads();
    if (t < 32) {
        float v = (t < NWARP) ? red[t] : -1e30f;
        #pragma unroll
        for (int o = 2; o; o >>= 1) v = fmaxf(v, __shfl_xor_sync(0xffffffffu, v, o));
        if (t == 0) red[2 * NWARP] = v;
    }
    __syncthreads();
    const float M = red[2 * NWARP];

    // ---------------- sum(exp) + weighted sum ----------------
    float s = 0.f, ws = 0.f;
    for (int p0 = t; p0 < NP; p0 += BLK) {
        float e = __expf(lsm[p0] - M);
        s += e;
        ws = fmaf(e, csm[p0], ws);
    }
    #pragma unroll
    for (int o = 16; o; o >>= 1) {
        s  += __shfl_xor_sync(0xffffffffu, s, o);
        ws += __shfl_xor_sync(0xffffffffu, ws, o);
    }
    if (lane == 0) { red[w] = s; red[NWARP + w] = ws; }
    __syncthreads();
    if (t == 0) {
        float S = 0.f, WS = 0.f;
        #pragma unroll
        for (int ww = 0; ww < NWARP; ww++) { S += red[ww]; WS += red[NWARP + ww]; }
        out[b] = WS / S;
    }
}

extern "C" void kernel_launch(void* const* d_in, const int* in_sizes, int n_in,
                              void* d_out, int out_size)
{
    const float* inputs = (const float*)d_in[0];
    const float* W1     = (const float*)d_in[1];
    const float* b1     = (const float*)d_in[2];
    const float* w2     = (const float*)d_in[3];
    const float* pvec   = (const float*)d_in[4];
    float* out = (float*)d_out;

    int B = in_sizes[0] / (NF * DIM);   // 8192
    afm_kernel<<<B, BLK>>>(inputs, W1, b1, w2, pvec, out);
}

// round 4
// speedup vs baseline: 7.1758x; 1.3817x over previous
#include <cuda_runtime.h>
#include <cuda_fp16.h>

#define NF    40
#define DIM   64
#define AD    32
#define NP    780
#define XSTR  80          // floats; (XSTR/4) % 8 == 4 -> conflict-free float4 xj loads
#define BLK   128
#define NWARP (BLK / 32)
#define NTILE 49          // ceil(780 / 16)

__device__ __forceinline__ unsigned h2u(__half2 h) {
    return *reinterpret_cast<unsigned*>(&h);
}

__device__ __forceinline__ void mma_f16(float* acc,
                                        unsigned a0, unsigned a1, unsigned a2, unsigned a3,
                                        unsigned b0, unsigned b1) {
    asm("mma.sync.aligned.m16n8k16.row.col.f32.f16.f16.f32 "
        "{%0,%1,%2,%3}, {%4,%5,%6,%7}, {%8,%9}, {%0,%1,%2,%3};"
        : "+f"(acc[0]), "+f"(acc[1]), "+f"(acc[2]), "+f"(acc[3])
        : "r"(a0), "r"(a1), "r"(a2), "r"(a3), "r"(b0), "r"(b1));
}

__global__ __launch_bounds__(BLK, 4)
void afm_kernel(const float* __restrict__ inputs,   // [B, 40, 64]
                const float* __restrict__ W1,       // [64, 32]
                const float* __restrict__ b1,       // [32]
                const float* __restrict__ w2,       // [32]
                const float* __restrict__ pvec,     // [64]
                float* __restrict__ out)            // [B]
{
    __shared__ __align__(16) float xs[NF * XSTR];   // d-permuted field embeddings
    __shared__ float lsm[NP];
    __shared__ float csm[NP];
    __shared__ float red[2 * NWARP + 2];
    __shared__ unsigned short pridx[NP];

    const int b    = blockIdx.x;
    const int t    = threadIdx.x;
    const int lane = t & 31;
    const int w    = t >> 5;
    const int q    = lane & 3;     // 0..3
    const int g    = lane >> 2;    // 0..7

    // ---------------- init: xs (permuted), pair table ----------------
    // physical col layout per 16-block: phys = 4*q + 2*r + e  <->  logical = 2*q + 8*r + e
    const float* xin = inputs + (size_t)b * (NF * DIM);
    #pragma unroll
    for (int idx = t; idx < NF * DIM; idx += BLK) {
        int r = idx >> 6, cphys = idx & 63;
        int kt = cphys >> 4, o = cphys & 15;
        int qq = o >> 2, rr = (o >> 1) & 1, e = o & 1;
        int dlog = kt * 16 + 2 * qq + 8 * rr + e;
        xs[r * XSTR + cphys] = xin[r * 64 + dlog];
    }
    if (t < NF - 1) {
        int i = t;
        int base = i * (2 * NF - 1 - i) / 2;
        for (int j = i + 1; j < NF; j++)
            pridx[base + (j - i - 1)] = (unsigned short)((i << 8) | j);
    }

    // ---------------- per-lane constant registers (from gmem) ----------------
    // B (W1) fragments, fp16 single precision (error 2^-11, validated in R2)
    unsigned bh[4][4][2];
    #pragma unroll
    for (int kt = 0; kt < 4; kt++)
        #pragma unroll
        for (int r = 0; r < 2; r++) {
            const int k0 = kt * 16 + 2 * q + 8 * r;
            #pragma unroll
            for (int nt = 0; nt < 4; nt++) {
                const int n = nt * 8 + g;
                bh[kt][nt][r] = h2u(__floats2half2_rn(W1[k0 * AD + n],
                                                      W1[(k0 + 1) * AD + n]));
            }
        }
    // pvec fragment: logical cols (c0, c0+1, c0+8, c0+9) per kt
    float4 pvr[4];
    #pragma unroll
    for (int kt = 0; kt < 4; kt++) {
        const int c0 = kt * 16 + 2 * q;
        pvr[kt] = make_float4(pvec[c0], pvec[c0 + 1], pvec[c0 + 8], pvec[c0 + 9]);
    }
    // epilogue constants: (b1[cc0], b1[cc1], w2[cc0], w2[cc1]) per nt
    float4 bw[4];
    #pragma unroll
    for (int nt = 0; nt < 4; nt++) {
        const int cc0 = nt * 8 + 2 * q;
        bw[nt] = make_float4(b1[cc0], b1[cc0 + 1], w2[cc0], w2[cc0 + 1]);
    }
    __syncthreads();

    // ---------------- mainloop ----------------
    for (int tile = w; tile < NTILE; tile += NWARP) {
        const int pA = tile * 16 + g;
        const int pB = pA + 8;
        const unsigned ppA = pridx[pA < NP ? pA : NP - 1];
        const unsigned ppB = pridx[pB < NP ? pB : NP - 1];
        const float* xiA = xs + (ppA >> 8) * XSTR + 4 * q;
        const float* xjA = xs + (ppA & 255) * XSTR + 4 * q;
        const float* xiB = xs + (ppB >> 8) * XSTR + 4 * q;
        const float* xjB = xs + (ppB & 255) * XSTR + 4 * q;

        float acc[4][4];
        #pragma unroll
        for (int nt = 0; nt < 4; nt++)
            #pragma unroll
            for (int r = 0; r < 4; r++) acc[nt][r] = 0.f;

        float cpA = 0.f, cpB = 0.f;

        #pragma unroll
        for (int kt = 0; kt < 4; kt++) {
            const int off = kt * 16;
            // one float4 per row: logical cols {c0, c0+1, c0+8, c0+9}
            float4 a4 = *(const float4*)(xiA + off);
            float4 u4 = *(const float4*)(xjA + off);
            float4 b4 = *(const float4*)(xiB + off);
            float4 v4 = *(const float4*)(xjB + off);

            float prA0 = a4.x * u4.x, prA1 = a4.y * u4.y;
            float prA8 = a4.z * u4.z, prA9 = a4.w * u4.w;
            float prB0 = b4.x * v4.x, prB1 = b4.y * v4.y;
            float prB8 = b4.z * v4.z, prB9 = b4.w * v4.w;

            float4 pv = pvr[kt];
            cpA = fmaf(prA0, pv.x, cpA); cpA = fmaf(prA1, pv.y, cpA);
            cpA = fmaf(prA8, pv.z, cpA); cpA = fmaf(prA9, pv.w, cpA);
            cpB = fmaf(prB0, pv.x, cpB); cpB = fmaf(prB1, pv.y, cpB);
            cpB = fmaf(prB8, pv.z, cpB); cpB = fmaf(prB9, pv.w, cpB);

            // fp16 hi + residual lo for A operand
            __half2 hA0 = __floats2half2_rn(prA0, prA1);
            __half2 hA8 = __floats2half2_rn(prA8, prA9);
            __half2 hB0 = __floats2half2_rn(prB0, prB1);
            __half2 hB8 = __floats2half2_rn(prB8, prB9);
            float2 fA0 = __half22float2(hA0), fA8 = __half22float2(hA8);
            float2 fB0 = __half22float2(hB0), fB8 = __half22float2(hB8);
            __half2 lA0 = __floats2half2_rn(prA0 - fA0.x, prA1 - fA0.y);
            __half2 lA8 = __floats2half2_rn(prA8 - fA8.x, prA9 - fA8.y);
            __half2 lB0 = __floats2half2_rn(prB0 - fB0.x, prB1 - fB0.y);
            __half2 lB8 = __floats2half2_rn(prB8 - fB8.x, prB9 - fB8.y);

            unsigned ah0 = h2u(hA0), ah1 = h2u(hB0), ah2 = h2u(hA8), ah3 = h2u(hB8);
            unsigned al0 = h2u(lA0), al1 = h2u(lB0), al2 = h2u(lA8), al3 = h2u(lB8);

            #pragma unroll
            for (int nt = 0; nt < 4; nt++) {
                mma_f16(acc[nt], ah0, ah1, ah2, ah3, bh[kt][nt][0], bh[kt][nt][1]);
                mma_f16(acc[nt], al0, al1, al2, al3, bh[kt][nt][0], bh[kt][nt][1]);
            }
        }

        // epilogue: relu(h + b1) . w2
        float s0 = 0.f, s1 = 0.f;
        #pragma unroll
        for (int nt = 0; nt < 4; nt++) {
            float4 c = bw[nt];
            s0 = fmaf(fmaxf(acc[nt][0] + c.x, 0.f), c.z, s0);
            s0 = fmaf(fmaxf(acc[nt][1] + c.y, 0.f), c.w, s0);
            s1 = fmaf(fmaxf(acc[nt][2] + c.x, 0.f), c.z, s1);
            s1 = fmaf(fmaxf(acc[nt][3] + c.y, 0.f), c.w, s1);
        }
        s0  += __shfl_xor_sync(0xffffffffu, s0, 1);
        s0  += __shfl_xor_sync(0xffffffffu, s0, 2);
        s1  += __shfl_xor_sync(0xffffffffu, s1, 1);
        s1  += __shfl_xor_sync(0xffffffffu, s1, 2);
        cpA += __shfl_xor_sync(0xffffffffu, cpA, 1);
        cpA += __shfl_xor_sync(0xffffffffu, cpA, 2);
        cpB += __shfl_xor_sync(0xffffffffu, cpB, 1);
        cpB += __shfl_xor_sync(0xffffffffu, cpB, 2);
        if (q == 0) {
            if (pA < NP) { lsm[pA] = s0; csm[pA] = cpA; }
            if (pB < NP) { lsm[pB] = s1; csm[pB] = cpB; }
        }
    }
    __syncthreads();

    // ---------------- softmax max ----------------
    float m = -1e30f;
    for (int p0 = t; p0 < NP; p0 += BLK) m = fmaxf(m, lsm[p0]);
    #pragma unroll
    for (int o = 16; o; o >>= 1) m = fmaxf(m, __shfl_xor_sync(0xffffffffu, m, o));
    if (lane == 0) red[w] = m;
    __syncthreads();
    if (t < 32) {
        float v = (t < NWARP) ? red[t] : -1e30f;
        #pragma unroll
        for (int o = 2; o; o >>= 1) v = fmaxf(v, __shfl_xor_sync(0xffffffffu, v, o));
        if (t == 0) red[2 * NWARP] = v;
    }
    __syncthreads();
    const float M = red[2 * NWARP];

    // ---------------- sum(exp) + weighted sum ----------------
    float s = 0.f, ws = 0.f;
    for (int p0 = t; p0 < NP; p0 += BLK) {
        float e = __expf(lsm[p0] - M);
        s += e;
        ws = fmaf(e, csm[p0], ws);
    }
    #pragma unroll
    for (int o = 16; o; o >>= 1) {
        s  += __shfl_xor_sync(0xffffffffu, s, o);
        ws += __shfl_xor_sync(0xffffffffu, ws, o);
    }
    if (lane == 0) { red[w] = s; red[NWARP + w] = ws; }
    __syncthreads();
    if (t == 0) {
        float S = 0.f, WS = 0.f;
        #pragma unroll
        for (int ww = 0; ww < NWARP; ww++) { S += red[ww]; WS += red[NWARP + ww]; }
        out[b] = WS / S;
    }
}

extern "C" void kernel_launch(void* const* d_in, const int* in_sizes, int n_in,
                              void* d_out, int out_size)
{
    const float* inputs = (const float*)d_in[0];
    const float* W1     = (const float*)d_in[1];
    const float* b1     = (const float*)d_in[2];
    const float* w2     = (const float*)d_in[3];
    const float* pvec   = (const float*)d_in[4];
    float* out = (float*)d_out;

    int B = in_sizes[0] / (NF * DIM);   // 8192
    afm_kernel<<<B, BLK>>>(inputs, W1, b1, w2, pvec, out);
}

// round 5
// speedup vs baseline: 9.0164x; 1.2565x over previous
#include <cuda_runtime.h>
#include <cuda_fp16.h>

#define NF    40
#define DIM   64
#define AD    32
#define NP    780
#define XSTR  80          // floats; conflict-free float4 gather pattern
#define BLK   128
#define NWARP (BLK / 32)
#define NTILE 49          // ceil(780 / 16)

__device__ __forceinline__ unsigned h2u(__half2 h) {
    return *reinterpret_cast<unsigned*>(&h);
}

// Blackwell packed f32x2 ops (PTX-only path)
__device__ __forceinline__ float2 ffma2(float2 a, float2 b, float2 c) {
    float2 d;
    asm("fma.rn.f32x2 %0, %1, %2, %3;"
        : "=l"(reinterpret_cast<unsigned long long&>(d))
        : "l"(reinterpret_cast<unsigned long long&>(a)),
          "l"(reinterpret_cast<unsigned long long&>(b)),
          "l"(reinterpret_cast<unsigned long long&>(c)));
    return d;
}
__device__ __forceinline__ float2 fmul2(float2 a, float2 b) {
    float2 d;
    asm("mul.rn.f32x2 %0, %1, %2;"
        : "=l"(reinterpret_cast<unsigned long long&>(d))
        : "l"(reinterpret_cast<unsigned long long&>(a)),
          "l"(reinterpret_cast<unsigned long long&>(b)));
    return d;
}

__device__ __forceinline__ void mma_f16(float* acc,
                                        unsigned a0, unsigned a1, unsigned a2, unsigned a3,
                                        unsigned b0, unsigned b1) {
    asm("mma.sync.aligned.m16n8k16.row.col.f32.f16.f16.f32 "
        "{%0,%1,%2,%3}, {%4,%5,%6,%7}, {%8,%9}, {%0,%1,%2,%3};"
        : "+f"(acc[0]), "+f"(acc[1]), "+f"(acc[2]), "+f"(acc[3])
        : "r"(a0), "r"(a1), "r"(a2), "r"(a3), "r"(b0), "r"(b1));
}

__global__ __launch_bounds__(BLK, 4)
void afm_kernel(const float* __restrict__ inputs,   // [B, 40, 64]
                const float* __restrict__ W1,       // [64, 32]
                const float* __restrict__ b1,       // [32]
                const float* __restrict__ w2,       // [32]
                const float* __restrict__ pvec,     // [64]
                float* __restrict__ out)            // [B]
{
    __shared__ __align__(16) float xs[NF * XSTR];   // d-permuted field embeddings
    __shared__ float lsm[NP];
    __shared__ float csm[NP];
    __shared__ float red[2 * NWARP + 2];
    __shared__ unsigned short pridx[NP];

    const int b    = blockIdx.x;
    const int t    = threadIdx.x;
    const int lane = t & 31;
    const int w    = t >> 5;
    const int q    = lane & 3;     // 0..3
    const int g    = lane >> 2;    // 0..7

    // ---------------- init: xs (permuted), pair table ----------------
    // physical col per 16-block: phys = 4*q + 2*r + e  <->  logical = 2*q + 8*r + e
    const float* xin = inputs + (size_t)b * (NF * DIM);
    #pragma unroll
    for (int idx = t; idx < NF * DIM; idx += BLK) {
        int r = idx >> 6, cphys = idx & 63;
        int kt = cphys >> 4, o = cphys & 15;
        int qq = o >> 2, rr = (o >> 1) & 1, e = o & 1;
        int dlog = kt * 16 + 2 * qq + 8 * rr + e;
        xs[r * XSTR + cphys] = xin[r * 64 + dlog];
    }
    if (t < NF - 1) {
        int i = t;
        int base = i * (2 * NF - 1 - i) / 2;
        for (int j = i + 1; j < NF; j++)
            pridx[base + (j - i - 1)] = (unsigned short)((i << 8) | j);
    }

    // ---------------- per-lane constant registers (from gmem) ----------------
    unsigned bh[4][4][2];
    #pragma unroll
    for (int kt = 0; kt < 4; kt++)
        #pragma unroll
        for (int r = 0; r < 2; r++) {
            const int k0 = kt * 16 + 2 * q + 8 * r;
            #pragma unroll
            for (int nt = 0; nt < 4; nt++) {
                const int n = nt * 8 + g;
                bh[kt][nt][r] = h2u(__floats2half2_rn(W1[k0 * AD + n],
                                                      W1[(k0 + 1) * AD + n]));
            }
        }
    // pvec fragments as float2 pairs: (c0,c0+1) and (c0+8,c0+9) per kt
    float2 pv0r[4], pv8r[4];
    #pragma unroll
    for (int kt = 0; kt < 4; kt++) {
        const int c0 = kt * 16 + 2 * q;
        pv0r[kt] = make_float2(pvec[c0],     pvec[c0 + 1]);
        pv8r[kt] = make_float2(pvec[c0 + 8], pvec[c0 + 9]);
    }
    float4 bw[4];
    #pragma unroll
    for (int nt = 0; nt < 4; nt++) {
        const int cc0 = nt * 8 + 2 * q;
        bw[nt] = make_float4(b1[cc0], b1[cc0 + 1], w2[cc0], w2[cc0 + 1]);
    }
    __syncthreads();

    // ---------------- mainloop ----------------
    for (int tile = w; tile < NTILE; tile += NWARP) {
        const int pA = tile * 16 + g;
        const int pB = pA + 8;
        const unsigned ppA = pridx[pA < NP ? pA : NP - 1];
        const unsigned ppB = pridx[pB < NP ? pB : NP - 1];
        const float* xiA = xs + (ppA >> 8) * XSTR + 4 * q;
        const float* xjA = xs + (ppA & 255) * XSTR + 4 * q;
        const float* xiB = xs + (ppB >> 8) * XSTR + 4 * q;
        const float* xjB = xs + (ppB & 255) * XSTR + 4 * q;

        float acc[4][4];
        #pragma unroll
        for (int nt = 0; nt < 4; nt++)
            #pragma unroll
            for (int r = 0; r < 4; r++) acc[nt][r] = 0.f;

        float2 cpA2 = make_float2(0.f, 0.f), cpB2 = make_float2(0.f, 0.f);

        #pragma unroll
        for (int kt = 0; kt < 4; kt++) {
            const int off = kt * 16;
            float4 a4 = *(const float4*)(xiA + off);
            float4 u4 = *(const float4*)(xjA + off);
            float4 b4 = *(const float4*)(xiB + off);
            float4 v4 = *(const float4*)(xjB + off);

            // packed products: {c0,c0+1} and {c0+8,c0+9}
            float2 prA0 = fmul2(make_float2(a4.x, a4.y), make_float2(u4.x, u4.y));
            float2 prA8 = fmul2(make_float2(a4.z, a4.w), make_float2(u4.z, u4.w));
            float2 prB0 = fmul2(make_float2(b4.x, b4.y), make_float2(v4.x, v4.y));
            float2 prB8 = fmul2(make_float2(b4.z, b4.w), make_float2(v4.z, v4.w));

            // pooled scalar accumulation (packed)
            cpA2 = ffma2(prA0, pv0r[kt], cpA2);
            cpA2 = ffma2(prA8, pv8r[kt], cpA2);
            cpB2 = ffma2(prB0, pv0r[kt], cpB2);
            cpB2 = ffma2(prB8, pv8r[kt], cpB2);

            // single fp16 A fragments
            unsigned ah0 = h2u(__floats2half2_rn(prA0.x, prA0.y));
            unsigned ah1 = h2u(__floats2half2_rn(prB0.x, prB0.y));
            unsigned ah2 = h2u(__floats2half2_rn(prA8.x, prA8.y));
            unsigned ah3 = h2u(__floats2half2_rn(prB8.x, prB8.y));

            #pragma unroll
            for (int nt = 0; nt < 4; nt++)
                mma_f16(acc[nt], ah0, ah1, ah2, ah3, bh[kt][nt][0], bh[kt][nt][1]);
        }

        // epilogue: relu(h + b1) . w2
        float s0 = 0.f, s1 = 0.f;
        #pragma unroll
        for (int nt = 0; nt < 4; nt++) {
            float4 c = bw[nt];
            s0 = fmaf(fmaxf(acc[nt][0] + c.x, 0.f), c.z, s0);
            s0 = fmaf(fmaxf(acc[nt][1] + c.y, 0.f), c.w, s0);
            s1 = fmaf(fmaxf(acc[nt][2] + c.x, 0.f), c.z, s1);
            s1 = fmaf(fmaxf(acc[nt][3] + c.y, 0.f), c.w, s1);
        }
        float cpA = cpA2.x + cpA2.y;
        float cpB = cpB2.x + cpB2.y;
        s0  += __shfl_xor_sync(0xffffffffu, s0, 1);
        s0  += __shfl_xor_sync(0xffffffffu, s0, 2);
        s1  += __shfl_xor_sync(0xffffffffu, s1, 1);
        s1  += __shfl_xor_sync(0xffffffffu, s1, 2);
        cpA += __shfl_xor_sync(0xffffffffu, cpA, 1);
        cpA += __shfl_xor_sync(0xffffffffu, cpA, 2);
        cpB += __shfl_xor_sync(0xffffffffu, cpB, 1);
        cpB += __shfl_xor_sync(0xffffffffu, cpB, 2);
        if (q == 0) {
            if (pA < NP) { lsm[pA] = s0; csm[pA] = cpA; }
            if (pB < NP) { lsm[pB] = s1; csm[pB] = cpB; }
        }
    }
    __syncthreads();

    // ---------------- softmax max ----------------
    float m = -1e30f;
    for (int p0 = t; p0 < NP; p0 += BLK) m = fmaxf(m, lsm[p0]);
    #pragma unroll
    for (int o = 16; o; o >>= 1) m = fmaxf(m, __shfl_xor_sync(0xffffffffu, m, o));
    if (lane == 0) red[w] = m;
    __syncthreads();
    if (t < 32) {
        float v = (t < NWARP) ? red[t] : -1e30f;
        #pragma unroll
        for (int o = 2; o; o >>= 1) v = fmaxf(v, __shfl_xor_sync(0xffffffffu, v, o));
        if (t == 0) red[2 * NWARP] = v;
    }
    __syncthreads();
    const float M = red[2 * NWARP];

    // ---------------- sum(exp) + weighted sum ----------------
    float s = 0.f, ws = 0.f;
    for (int p0 = t; p0 < NP; p0 += BLK) {
        float e = __expf(lsm[p0] - M);
        s += e;
        ws = fmaf(e, csm[p0], ws);
    }
    #pragma unroll
    for (int o = 16; o; o >>= 1) {
        s  += __shfl_xor_sync(0xffffffffu, s, o);
        ws += __shfl_xor_sync(0xffffffffu, ws, o);
    }
    if (lane == 0) { red[w] = s; red[NWARP + w] = ws; }
    __syncthreads();
    if (t == 0) {
        float S = 0.f, WS = 0.f;
        #pragma unroll
        for (int ww = 0; ww < NWARP; ww++) { S += red[ww]; WS += red[NWARP + ww]; }
        out[b] = WS / S;
    }
}

extern "C" void kernel_launch(void* const* d_in, const int* in_sizes, int n_in,
                              void* d_out, int out_size)
{
    const float* inputs = (const float*)d_in[0];
    const float* W1     = (const float*)d_in[1];
    const float* b1     = (const float*)d_in[2];
    const float* w2     = (const float*)d_in[3];
    const float* pvec   = (const float*)d_in[4];
    float* out = (float*)d_out;

    int B = in_sizes[0] / (NF * DIM);   // 8192
    afm_kernel<<<B, BLK>>>(inputs, W1, b1, w2, pvec, out);
}

// round 6
// speedup vs baseline: 11.4876x; 1.2741x over previous
#include <cuda_runtime.h>
#include <cuda_fp16.h>

#define NF    40
#define DIM   64
#define AD    32
#define NP    780
#define XSTRH 80          // half units; 160B row stride -> phase-conflict-free LDS.64
#define BLK   128
#define NWARP (BLK / 32)
#define NTILE 49          // ceil(780 / 16)

__device__ __forceinline__ unsigned h2u(__half2 h) {
    return *reinterpret_cast<unsigned*>(&h);
}

__device__ __forceinline__ void mma_f16(float* acc,
                                        unsigned a0, unsigned a1, unsigned a2, unsigned a3,
                                        unsigned b0, unsigned b1) {
    asm("mma.sync.aligned.m16n8k16.row.col.f32.f16.f16.f32 "
        "{%0,%1,%2,%3}, {%4,%5,%6,%7}, {%8,%9}, {%0,%1,%2,%3};"
        : "+f"(acc[0]), "+f"(acc[1]), "+f"(acc[2]), "+f"(acc[3])
        : "r"(a0), "r"(a1), "r"(a2), "r"(a3), "r"(b0), "r"(b1));
}

__global__ __launch_bounds__(BLK, 5)
void afm_kernel(const float* __restrict__ inputs,   // [B, 40, 64]
                const float* __restrict__ W1,       // [64, 32]
                const float* __restrict__ b1,       // [32]
                const float* __restrict__ w2,       // [32]
                const float* __restrict__ pvec,     // [64]
                float* __restrict__ out)            // [B]
{
    __shared__ __align__(16) __half xs[NF * XSTRH];   // d-permuted fp16 embeddings
    __shared__ float lsm[NP];
    __shared__ float csm[NP];
    __shared__ float red[2 * NWARP + 2];
    __shared__ unsigned short pridx[NP];

    const int b    = blockIdx.x;
    const int t    = threadIdx.x;
    const int lane = t & 31;
    const int w    = t >> 5;
    const int q    = lane & 3;     // 0..3
    const int g    = lane >> 2;    // 0..7

    // ---------------- init: xs (permuted fp16), pair table ----------------
    // phys half-pair m (0..31) within row: kt = m>>3, mm = m&7, q=mm>>1, r=mm&1
    //   -> logical d0 = kt*16 + 2*q + 8*r (d0, d0+1 consecutive)
    const float* xin = inputs + (size_t)b * (NF * DIM);
    #pragma unroll
    for (int idx = t; idx < NF * 32; idx += BLK) {
        int r = idx >> 5, m = idx & 31;
        int kt = m >> 3, mm = m & 7;
        int dlog = kt * 16 + 2 * (mm >> 1) + 8 * (mm & 1);
        float2 v = *(const float2*)(xin + r * 64 + dlog);
        *(__half2*)(xs + r * XSTRH + 2 * m) = __floats2half2_rn(v.x, v.y);
    }
    if (t < NF - 1) {
        int i = t;
        int base = i * (2 * NF - 1 - i) / 2;
        for (int j = i + 1; j < NF; j++)
            pridx[base + (j - i - 1)] = (unsigned short)((i << 8) | j);
    }

    // ---------------- B fragments: W1 (nt 0..3) + [p_hi, p_lo, 0...] (nt 4) ----------------
    unsigned bh[4][5][2];
    #pragma unroll
    for (int kt = 0; kt < 4; kt++)
        #pragma unroll
        for (int r = 0; r < 2; r++) {
            const int k0 = kt * 16 + 2 * q + 8 * r;
            #pragma unroll
            for (int nt = 0; nt < 4; nt++) {
                const int n = nt * 8 + g;
                bh[kt][nt][r] = h2u(__floats2half2_rn(W1[k0 * AD + n],
                                                      W1[(k0 + 1) * AD + n]));
            }
            // nt4: col 0 = p_hi, col 1 = p_lo (residual), cols 2..7 = 0
            float p0 = pvec[k0], p1 = pvec[k0 + 1];
            __half2 phi = __floats2half2_rn(p0, p1);
            float2 pf = __half22float2(phi);
            __half2 plo = __floats2half2_rn(p0 - pf.x, p1 - pf.y);
            unsigned bv = 0;
            if (g == 0) bv = h2u(phi);
            else if (g == 1) bv = h2u(plo);
            bh[kt][4][r] = bv;
        }
    float4 bw[4];
    #pragma unroll
    for (int nt = 0; nt < 4; nt++) {
        const int cc0 = nt * 8 + 2 * q;
        bw[nt] = make_float4(b1[cc0], b1[cc0 + 1], w2[cc0], w2[cc0 + 1]);
    }
    __syncthreads();

    // ---------------- mainloop ----------------
    for (int tile = w; tile < NTILE; tile += NWARP) {
        const int pA = tile * 16 + g;
        const int pB = pA + 8;
        const unsigned ppA = pridx[pA < NP ? pA : NP - 1];
        const unsigned ppB = pridx[pB < NP ? pB : NP - 1];
        const __half* xiA = xs + (ppA >> 8) * XSTRH + 4 * q;
        const __half* xjA = xs + (ppA & 255) * XSTRH + 4 * q;
        const __half* xiB = xs + (ppB >> 8) * XSTRH + 4 * q;
        const __half* xjB = xs + (ppB & 255) * XSTRH + 4 * q;

        float acc[5][4];
        #pragma unroll
        for (int nt = 0; nt < 5; nt++)
            #pragma unroll
            for (int r = 0; r < 4; r++) acc[nt][r] = 0.f;

        #pragma unroll
        for (int kt = 0; kt < 4; kt++) {
            const int off = kt * 16;   // halves
            __half2 iA0, iA1, jA0, jA1, iB0, iB1, jB0, jB1;
            { uint2 v = *(const uint2*)(xiA + off); iA0 = *(__half2*)&v.x; iA1 = *(__half2*)&v.y; }
            { uint2 v = *(const uint2*)(xjA + off); jA0 = *(__half2*)&v.x; jA1 = *(__half2*)&v.y; }
            { uint2 v = *(const uint2*)(xiB + off); iB0 = *(__half2*)&v.x; iB1 = *(__half2*)&v.y; }
            { uint2 v = *(const uint2*)(xjB + off); jB0 = *(__half2*)&v.x; jB1 = *(__half2*)&v.y; }

            // fp16 products ARE the A fragments
            unsigned ah0 = h2u(__hmul2(iA0, jA0));   // row g,   k = 2q,2q+1
            unsigned ah1 = h2u(__hmul2(iB0, jB0));   // row g+8
            unsigned ah2 = h2u(__hmul2(iA1, jA1));   // row g,   k = 2q+8,2q+9
            unsigned ah3 = h2u(__hmul2(iB1, jB1));   // row g+8

            #pragma unroll
            for (int nt = 0; nt < 5; nt++)
                mma_f16(acc[nt], ah0, ah1, ah2, ah3, bh[kt][nt][0], bh[kt][nt][1]);
        }

        // epilogue: relu(h + b1) . w2
        float s0 = 0.f, s1 = 0.f;
        #pragma unroll
        for (int nt = 0; nt < 4; nt++) {
            float4 c = bw[nt];
            s0 = fmaf(fmaxf(acc[nt][0] + c.x, 0.f), c.z, s0);
            s0 = fmaf(fmaxf(acc[nt][1] + c.y, 0.f), c.w, s0);
            s1 = fmaf(fmaxf(acc[nt][2] + c.x, 0.f), c.z, s1);
            s1 = fmaf(fmaxf(acc[nt][3] + c.y, 0.f), c.w, s1);
        }
        s0 += __shfl_xor_sync(0xffffffffu, s0, 1);
        s0 += __shfl_xor_sync(0xffffffffu, s0, 2);
        s1 += __shfl_xor_sync(0xffffffffu, s1, 1);
        s1 += __shfl_xor_sync(0xffffffffu, s1, 2);
        if (q == 0) {
            // cp lives on q==0: acc[4][0]=prod.p_hi, acc[4][1]=prod.p_lo (cols 0,1)
            if (pA < NP) { lsm[pA] = s0; csm[pA] = acc[4][0] + acc[4][1]; }
            if (pB < NP) { lsm[pB] = s1; csm[pB] = acc[4][2] + acc[4][3]; }
        }
    }
    __syncthreads();

    // ---------------- softmax max ----------------
    float m = -1e30f;
    for (int p0 = t; p0 < NP; p0 += BLK) m = fmaxf(m, lsm[p0]);
    #pragma unroll
    for (int o = 16; o; o >>= 1) m = fmaxf(m, __shfl_xor_sync(0xffffffffu, m, o));
    if (lane == 0) red[w] = m;
    __syncthreads();
    if (t < 32) {
        float v = (t < NWARP) ? red[t] : -1e30f;
        #pragma unroll
        for (int o = 2; o; o >>= 1) v = fmaxf(v, __shfl_xor_sync(0xffffffffu, v, o));
        if (t == 0) red[2 * NWARP] = v;
    }
    __syncthreads();
    const float M = red[2 * NWARP];

    // ---------------- sum(exp) + weighted sum ----------------
    float s = 0.f, ws = 0.f;
    for (int p0 = t; p0 < NP; p0 += BLK) {
        float e = __expf(lsm[p0] - M);
        s += e;
        ws = fmaf(e, csm[p0], ws);
    }
    #pragma unroll
    for (int o = 16; o; o >>= 1) {
        s  += __shfl_xor_sync(0xffffffffu, s, o);
        ws += __shfl_xor_sync(0xffffffffu, ws, o);
    }
    if (lane == 0) { red[w] = s; red[NWARP + w] = ws; }
    __syncthreads();
    if (t == 0) {
        float S = 0.f, WS = 0.f;
        #pragma unroll
        for (int ww = 0; ww < NWARP; ww++) { S += red[ww]; WS += red[NWARP + ww]; }
        out[b] = WS / S;
    }
}

extern "C" void kernel_launch(void* const* d_in, const int* in_sizes, int n_in,
                              void* d_out, int out_size)
{
    const float* inputs = (const float*)d_in[0];
    const float* W1     = (const float*)d_in[1];
    const float* b1     = (const float*)d_in[2];
    const float* w2     = (const float*)d_in[3];
    const float* pvec   = (const float*)d_in[4];
    float* out = (float*)d_out;

    int B = in_sizes[0] / (NF * DIM);   // 8192
    afm_kernel<<<B, BLK>>>(inputs, W1, b1, w2, pvec, out);
}

// round 7
// speedup vs baseline: 11.8937x; 1.0353x over previous
#include <cuda_runtime.h>
#include <cuda_fp16.h>

#define NF    40
#define DIM   64
#define AD    32
#define NP    780
#define XSTRH 72          // halves; 144B row stride; (XSTRH/8) odd -> distinct 16B bank groups
#define BLK   128
#define NWARP (BLK / 32)
#define NTILE 49          // ceil(780 / 16)

__device__ __forceinline__ unsigned h2u(__half2 h) {
    return *reinterpret_cast<unsigned*>(&h);
}

__device__ __forceinline__ void mma_f16(float* acc,
                                        unsigned a0, unsigned a1, unsigned a2, unsigned a3,
                                        unsigned b0, unsigned b1) {
    asm("mma.sync.aligned.m16n8k16.row.col.f32.f16.f16.f32 "
        "{%0,%1,%2,%3}, {%4,%5,%6,%7}, {%8,%9}, {%0,%1,%2,%3};"
        : "+f"(acc[0]), "+f"(acc[1]), "+f"(acc[2]), "+f"(acc[3])
        : "r"(a0), "r"(a1), "r"(a2), "r"(a3), "r"(b0), "r"(b1));
}

__device__ __forceinline__ void ldsm_x4(unsigned& r0, unsigned& r1,
                                        unsigned& r2, unsigned& r3, unsigned addr) {
    asm volatile("ldmatrix.sync.aligned.m8n8.x4.shared.b16 {%0,%1,%2,%3}, [%4];"
        : "=r"(r0), "=r"(r1), "=r"(r2), "=r"(r3) : "r"(addr));
}

__global__ __launch_bounds__(BLK, 5)
void afm_kernel(const float* __restrict__ inputs,   // [B, 40, 64]
                const float* __restrict__ W1,       // [64, 32]
                const float* __restrict__ b1,       // [32]
                const float* __restrict__ w2,       // [32]
                const float* __restrict__ pvec,     // [64]
                float* __restrict__ out)            // [B]
{
    __shared__ __align__(16) __half xs[NF * XSTRH];   // natural-order fp16 embeddings
    __shared__ float lsm[NP];
    __shared__ float csm[NP];
    __shared__ float red[2 * NWARP + 2];
    __shared__ unsigned short pridx[NP];

    const int b    = blockIdx.x;
    const int t    = threadIdx.x;
    const int lane = t & 31;
    const int w    = t >> 5;
    const int q    = lane & 3;     // 0..3
    const int g    = lane >> 2;    // 0..7

    // ---------------- init: xs (fp16, natural d order), pair table ----------------
    const float* xin = inputs + (size_t)b * (NF * DIM);
    #pragma unroll
    for (int idx = t; idx < NF * 16; idx += BLK) {
        int r = idx >> 4, c4 = (idx & 15) << 2;       // 4 floats per step
        float4 v = *(const float4*)(xin + r * 64 + c4);
        __half2 h0 = __floats2half2_rn(v.x, v.y);
        __half2 h1 = __floats2half2_rn(v.z, v.w);
        *(__half2*)(xs + r * XSTRH + c4)     = h0;
        *(__half2*)(xs + r * XSTRH + c4 + 2) = h1;
    }
    if (t < NF - 1) {
        int i = t;
        int base = i * (2 * NF - 1 - i) / 2;
        for (int j = i + 1; j < NF; j++)
            pridx[base + (j - i - 1)] = (unsigned short)((i << 8) | j);
    }

    // ---------------- B fragments: W1 (nt 0..3) + [p_hi, p_lo, 0...] (nt 4) ----------------
    unsigned bh[4][5][2];
    #pragma unroll
    for (int kt = 0; kt < 4; kt++)
        #pragma unroll
        for (int r = 0; r < 2; r++) {
            const int k0 = kt * 16 + 2 * q + 8 * r;
            #pragma unroll
            for (int nt = 0; nt < 4; nt++) {
                const int n = nt * 8 + g;
                bh[kt][nt][r] = h2u(__floats2half2_rn(W1[k0 * AD + n],
                                                      W1[(k0 + 1) * AD + n]));
            }
            float p0 = pvec[k0], p1 = pvec[k0 + 1];
            __half2 phi = __floats2half2_rn(p0, p1);
            float2 pf = __half22float2(phi);
            __half2 plo = __floats2half2_rn(p0 - pf.x, p1 - pf.y);
            unsigned bv = 0;
            if (g == 0) bv = h2u(phi);
            else if (g == 1) bv = h2u(plo);
            bh[kt][4][r] = bv;
        }
    float4 bw[4];
    #pragma unroll
    for (int nt = 0; nt < 4; nt++) {
        const int cc0 = nt * 8 + 2 * q;
        bw[nt] = make_float4(b1[cc0], b1[cc0 + 1], w2[cc0], w2[cc0 + 1]);
    }
    const unsigned xs_base = (unsigned)__cvta_generic_to_shared(xs);
    __syncthreads();

    // ---------------- mainloop ----------------
    for (int tile = w; tile < NTILE; tile += NWARP) {
        // ldmatrix per-lane row assignment:
        //   lanes 0-7  : matrix0 = rows 0-7,  k 0-7   (pair tile*16 + lane,    koff 0)
        //   lanes 8-15 : matrix1 = rows 8-15, k 0-7   (pair tile*16 + lane,    koff 0)
        //   lanes 16-23: matrix2 = rows 0-7,  k 8-15  (pair tile*16 + lane-16, koff 8)
        //   lanes 24-31: matrix3 = rows 8-15, k 8-15  (pair tile*16 + lane-16, koff 8)
        int pl = tile * 16 + (lane & 15);
        pl = pl < NP ? pl : NP - 1;
        const unsigned pp = pridx[pl];
        const unsigned koff = (lane >> 4) << 3;       // 0 or 8 halves
        const unsigned xi_addr = xs_base + 2u * ((pp >> 8) * XSTRH + koff);
        const unsigned xj_addr = xs_base + 2u * ((pp & 255u) * XSTRH + koff);

        float acc[5][4];
        #pragma unroll
        for (int nt = 0; nt < 5; nt++)
            #pragma unroll
            for (int r = 0; r < 4; r++) acc[nt][r] = 0.f;

        #pragma unroll
        for (int kt = 0; kt < 4; kt++) {
            unsigned xi0, xi1, xi2, xi3, xj0, xj1, xj2, xj3;
            ldsm_x4(xi0, xi1, xi2, xi3, xi_addr + kt * 32);
            ldsm_x4(xj0, xj1, xj2, xj3, xj_addr + kt * 32);

            unsigned ah0 = h2u(__hmul2(*(__half2*)&xi0, *(__half2*)&xj0));
            unsigned ah1 = h2u(__hmul2(*(__half2*)&xi1, *(__half2*)&xj1));
            unsigned ah2 = h2u(__hmul2(*(__half2*)&xi2, *(__half2*)&xj2));
            unsigned ah3 = h2u(__hmul2(*(__half2*)&xi3, *(__half2*)&xj3));

            #pragma unroll
            for (int nt = 0; nt < 5; nt++)
                mma_f16(acc[nt], ah0, ah1, ah2, ah3, bh[kt][nt][0], bh[kt][nt][1]);
        }

        // epilogue: relu(h + b1) . w2
        float s0 = 0.f, s1 = 0.f;
        #pragma unroll
        for (int nt = 0; nt < 4; nt++) {
            float4 c = bw[nt];
            s0 = fmaf(fmaxf(acc[nt][0] + c.x, 0.f), c.z, s0);
            s0 = fmaf(fmaxf(acc[nt][1] + c.y, 0.f), c.w, s0);
            s1 = fmaf(fmaxf(acc[nt][2] + c.x, 0.f), c.z, s1);
            s1 = fmaf(fmaxf(acc[nt][3] + c.y, 0.f), c.w, s1);
        }
        s0 += __shfl_xor_sync(0xffffffffu, s0, 1);
        s0 += __shfl_xor_sync(0xffffffffu, s0, 2);
        s1 += __shfl_xor_sync(0xffffffffu, s1, 1);
        s1 += __shfl_xor_sync(0xffffffffu, s1, 2);
        if (q == 0) {
            const int pA = tile * 16 + g;
            const int pB = pA + 8;
            if (pA < NP) { lsm[pA] = s0; csm[pA] = acc[4][0] + acc[4][1]; }
            if (pB < NP) { lsm[pB] = s1; csm[pB] = acc[4][2] + acc[4][3]; }
        }
    }
    __syncthreads();

    // ---------------- softmax max ----------------
    float m = -1e30f;
    for (int p0 = t; p0 < NP; p0 += BLK) m = fmaxf(m, lsm[p0]);
    #pragma unroll
    for (int o = 16; o; o >>= 1) m = fmaxf(m, __shfl_xor_sync(0xffffffffu, m, o));
    if (lane == 0) red[w] = m;
    __syncthreads();
    if (t < 32) {
        float v = (t < NWARP) ? red[t] : -1e30f;
        #pragma unroll
        for (int o = 2; o; o >>= 1) v = fmaxf(v, __shfl_xor_sync(0xffffffffu, v, o));
        if (t == 0) red[2 * NWARP] = v;
    }
    __syncthreads();
    const float M = red[2 * NWARP];

    // ---------------- sum(exp) + weighted sum ----------------
    float s = 0.f, ws = 0.f;
    for (int p0 = t; p0 < NP; p0 += BLK) {
        float e = __expf(lsm[p0] - M);
        s += e;
        ws = fmaf(e, csm[p0], ws);
    }
    #pragma unroll
    for (int o = 16; o; o >>= 1) {
        s  += __shfl_xor_sync(0xffffffffu, s, o);
        ws += __shfl_xor_sync(0xffffffffu, ws, o);
    }
    if (lane == 0) { red[w] = s; red[NWARP + w] = ws; }
    __syncthreads();
    if (t == 0) {
        float S = 0.f, WS = 0.f;
        #pragma unroll
        for (int ww = 0; ww < NWARP; ww++) { S += red[ww]; WS += red[NWARP + ww]; }
        out[b] = WS / S;
    }
}

extern "C" void kernel_launch(void* const* d_in, const int* in_sizes, int n_in,
                              void* d_out, int out_size)
{
    const float* inputs = (const float*)d_in[0];
    const float* W1     = (const float*)d_in[1];
    const float* b1     = (const float*)d_in[2];
    const float* w2     = (const float*)d_in[3];
    const float* pvec   = (const float*)d_in[4];
    float* out = (float*)d_out;

    int B = in_sizes[0] / (NF * DIM);   // 8192
    afm_kernel<<<B, BLK>>>(inputs, W1, b1, w2, pvec, out);
}